// round 15
// baseline (speedup 1.0000x reference)
#include <cuda_runtime.h>
#include <cuda_fp16.h>
#include <math.h>
#include <stdint.h>

// Problem constants
#define BATCH 2
#define TT    4096
#define DIM   1024
#define MROWS (BATCH * TT)     // 8192
#define HEADS 16
#define HS    64

// ---------------- scratch (static device globals; no allocation) ------------
__device__ __half g_xh  [(size_t)MROWS * DIM];          // LN1 out (GEMM A + residual)
__device__ __half g_qkv [(size_t)MROWS * 3 * DIM];      // [q|k|v] fp16
__device__ __half g_at  [(size_t)MROWS * 2 * DIM];      // attn out fp16
__device__ __half g_yh  [(size_t)MROWS * DIM];          // fb out fp16
__device__ __half g_zh  [(size_t)MROWS * DIM];          // LN2 out fp16
__device__ __half g_wqkvT[(size_t)(3 * DIM) * DIM];     // 3072 x 1024 (N-major)
__device__ __half g_woT [(size_t)DIM * DIM];            // 1024 x 1024
__device__ __half g_wfbT[(size_t)DIM * 2 * DIM];        // 1024 x 2048
__device__ float g_bqkv[3 * DIM];

// ---------------- PTX helpers ----------------------------------------------
__device__ __forceinline__ uint32_t s2u(const void* p) {
    uint32_t a;
    asm("{ .reg .u64 t; cvta.to.shared.u64 t, %1; cvt.u32.u64 %0, t; }"
        : "=r"(a) : "l"(p));
    return a;
}
__device__ __forceinline__ void cpa16(uint32_t s, const void* g) {
    asm volatile("cp.async.cg.shared.global [%0], [%1], 16;" :: "r"(s), "l"(g));
}
#define CP_COMMIT() asm volatile("cp.async.commit_group;" ::: "memory")
#define CP_WAIT1()  asm volatile("cp.async.wait_group 1;" ::: "memory")

#define LDSM4(r0, r1, r2, r3, addr) \
    asm volatile("ldmatrix.sync.aligned.m8n8.x4.shared.b16 {%0,%1,%2,%3}, [%4];" \
        : "=r"(r0), "=r"(r1), "=r"(r2), "=r"(r3) : "r"(addr))

#define MMA16816(d, a, b) \
    asm volatile("mma.sync.aligned.m16n8k16.row.col.f32.f16.f16.f32 " \
        "{%0,%1,%2,%3},{%4,%5,%6,%7},{%8,%9},{%0,%1,%2,%3};" \
        : "+f"((d)[0]), "+f"((d)[1]), "+f"((d)[2]), "+f"((d)[3]) \
        : "r"((a)[0]), "r"((a)[1]), "r"((a)[2]), "r"((a)[3]), \
          "r"((b)[0]), "r"((b)[1]))

// ---------------- prep: LN1 + wqkv transpose + bias concat ------------------
#define WQKV_TILES 3072             // Wq, Wk, Wv: 3 x 1024 32x32 tiles
#define BBLOCKS 12                  // 3072 / 256

__global__ void prep_kernel(const float* __restrict__ x,
                            const float* __restrict__ g1,
                            const float* __restrict__ b1,
                            __half* __restrict__ xh,
                            const float* __restrict__ Wq,
                            const float* __restrict__ Wk,
                            const float* __restrict__ Wv,
                            const float* __restrict__ bq,
                            const float* __restrict__ bk,
                            const float* __restrict__ bv,
                            float* __restrict__ bqkv)
{
    __shared__ float rs[8], rss[8];
    __shared__ float ts[32][33];
    int blk = blockIdx.x;
    int tid = threadIdx.x;

    if (blk < MROWS) {
        int row = blk;
        float4 v = ((const float4*)(x + (size_t)row * DIM))[tid];
        float s  = v.x + v.y + v.z + v.w;
        float ss = v.x*v.x + v.y*v.y + v.z*v.z + v.w*v.w;
        #pragma unroll
        for (int o = 16; o; o >>= 1) {
            s  += __shfl_xor_sync(0xffffffffu, s,  o);
            ss += __shfl_xor_sync(0xffffffffu, ss, o);
        }
        int wid = tid >> 5, lid = tid & 31;
        if (lid == 0) { rs[wid] = s; rss[wid] = ss; }
        __syncthreads();
        float tots = 0.f, totss = 0.f;
        #pragma unroll
        for (int i = 0; i < 8; i++) { tots += rs[i]; totss += rss[i]; }
        float mean = tots * (1.0f / DIM);
        float var  = totss * (1.0f / DIM) - mean * mean;
        float inv  = rsqrtf(var + 1e-6f);
        float4 gg = ((const float4*)g1)[tid], bb = ((const float4*)b1)[tid];
        float ox = (v.x - mean) * inv * gg.x + bb.x;
        float oy = (v.y - mean) * inv * gg.y + bb.y;
        float oz = (v.z - mean) * inv * gg.z + bb.z;
        float ow = (v.w - mean) * inv * gg.w + bb.w;
        __half* base = xh + (size_t)row * DIM + tid * 4;
        *(__half2*)(base)     = __halves2half2(__float2half(ox), __float2half(oy));
        *(__half2*)(base + 2) = __halves2half2(__float2half(oz), __float2half(ow));
        return;
    }
    blk -= MROWS;
    if (blk < WQKV_TILES) {
        int which = blk >> 10;
        int tile  = blk & 1023;
        const float* W = (which == 0) ? Wq : (which == 1) ? Wk : Wv;
        int nofs = which * DIM;
        int k0 = (tile >> 5) * 32;
        int n0 = (tile & 31) * 32;
        int r = tid >> 5, c = tid & 31;
        #pragma unroll
        for (int i = 0; i < 4; i++)
            ts[r + 8 * i][c] = W[(size_t)(k0 + r + 8 * i) * DIM + n0 + c];
        __syncthreads();
        #pragma unroll
        for (int i = 0; i < 4; i++) {
            int n = n0 + r + 8 * i;
            g_wqkvT[(size_t)(nofs + n) * DIM + k0 + c] = __float2half(ts[c][r + 8 * i]);
        }
        return;
    }
    blk -= WQKV_TILES;
    int i = blk * 256 + tid;
    if (i < DIM) bqkv[i] = bq[i];
    else if (i < 2 * DIM) bqkv[i] = bk[i - DIM];
    else if (i < 3 * DIM) bqkv[i] = bv[i - 2 * DIM];
}

// ---------------- LN2: fp16 y + fp16 residual -> fp16 out -------------------
__global__ void ln2_kernel(const __half* __restrict__ y,
                           const __half* __restrict__ res,
                           const float* __restrict__ g,
                           const float* __restrict__ b,
                           __half* __restrict__ h_out)
{
    __shared__ float rs[8], rss[8];
    int row = blockIdx.x;
    int tid = threadIdx.x;
    uint2 uy = ((const uint2*)(y   + (size_t)row * DIM))[tid];
    uint2 ur = ((const uint2*)(res + (size_t)row * DIM))[tid];
    float2 y0 = __half22float2(*(__half2*)&uy.x);
    float2 y1 = __half22float2(*(__half2*)&uy.y);
    float2 r0 = __half22float2(*(__half2*)&ur.x);
    float2 r1 = __half22float2(*(__half2*)&ur.y);
    float4 v = make_float4(y0.x + r0.x, y0.y + r0.y, y1.x + r1.x, y1.y + r1.y);
    float s  = v.x + v.y + v.z + v.w;
    float ss = v.x*v.x + v.y*v.y + v.z*v.z + v.w*v.w;
    #pragma unroll
    for (int o = 16; o; o >>= 1) {
        s  += __shfl_xor_sync(0xffffffffu, s,  o);
        ss += __shfl_xor_sync(0xffffffffu, ss, o);
    }
    int wid = tid >> 5, lid = tid & 31;
    if (lid == 0) { rs[wid] = s; rss[wid] = ss; }
    __syncthreads();
    float tots = 0.f, totss = 0.f;
    #pragma unroll
    for (int i = 0; i < 8; i++) { tots += rs[i]; totss += rss[i]; }
    float mean = tots * (1.0f / DIM);
    float var  = totss * (1.0f / DIM) - mean * mean;
    float inv  = rsqrtf(var + 1e-6f);
    float4 gg = ((const float4*)g)[tid], bb = ((const float4*)b)[tid];
    float ox = (v.x - mean) * inv * gg.x + bb.x;
    float oy = (v.y - mean) * inv * gg.y + bb.y;
    float oz = (v.z - mean) * inv * gg.z + bb.z;
    float ow = (v.w - mean) * inv * gg.w + bb.w;
    __half* base = h_out + (size_t)row * DIM + tid * 4;
    *(__half2*)(base)     = __halves2half2(__float2half(ox), __float2half(oy));
    *(__half2*)(base + 2) = __halves2half2(__float2half(oz), __float2half(ow));
}

// ---------------- HMMA fp16 GEMM (templated: AUX tail transposes) -----------
#define STG_OP 16384
#define GSMEM  (3 * 2 * STG_OP)      // 98304
#define AUX_WO   1024
#define AUX_WFB  2048
#define AUX_TOT  (AUX_WO + AUX_WFB)  // 3072

__device__ __forceinline__ float gelu_exact(float x) {
    return 0.5f * x * (1.0f + erff(x * 0.7071067811865475f));
}

template<int AUX>
__global__ __launch_bounds__(128, 2)
void gemm_hmma(const __half* __restrict__ A, const __half* __restrict__ B,
               const float* __restrict__ bias, void* __restrict__ Cv,
               int KK, int ldc, int epi, int ntiles, int nx,
               const float* __restrict__ WoSrc, const float* __restrict__ WfbSrc)
{
    extern __shared__ char smem[];
    const int bid = blockIdx.x;
    const int tid = threadIdx.x;

    if (AUX && bid >= ntiles) {
        // ---- aux: coalesced 32x32 transpose (128 threads, 4 rows/pass) ----
        float (*ts)[33] = (float(*)[33])smem;
        int blk = bid - ntiles;
        const float* W; __half* O; int K, tile;
        if (blk < AUX_WO) { W = WoSrc; O = g_woT; K = DIM; tile = blk; }
        else { W = WfbSrc; O = g_wfbT; K = 2 * DIM; tile = blk - AUX_WO; }
        int k0 = (tile >> 5) * 32;
        int n0 = (tile & 31) * 32;
        int r = tid >> 5, c = tid & 31;
        #pragma unroll
        for (int i = 0; i < 8; i++)
            ts[r + 4 * i][c] = W[(size_t)(k0 + r + 4 * i) * DIM + n0 + c];
        __syncthreads();
        #pragma unroll
        for (int i = 0; i < 8; i++) {
            int n = n0 + r + 4 * i;
            O[(size_t)n * K + k0 + c] = __float2half(ts[c][r + 4 * i]);
        }
        return;
    }

    const uint32_t sb = s2u(smem);
    const int wid  = tid >> 5, lane = tid & 31;
    const int bx   = bid % nx, by = bid / nx;
    const int wm   = wid & 1;
    const int wn   = wid >> 1;
    const int NT   = KK >> 6;

    uint32_t sA[3], sB[3];
    #pragma unroll
    for (int s = 0; s < 3; s++) {
        sA[s] = sb + s * 2 * STG_OP;
        sB[s] = sA[s] + STG_OP;
    }

    const int lrow = tid >> 3;
    const uint32_t ssw = ((tid & 7) * 16) ^ ((lrow & 7) << 4);
    const __half* Ag = A + (size_t)(by * 128 + lrow) * KK + (tid & 7) * 8;
    const __half* Bg = B + (size_t)(bx * 128 + lrow) * KK + (tid & 7) * 8;

    auto load_stage = [&](int s, int kt) {
        size_t kof = (size_t)kt * 64;
        #pragma unroll
        for (int i = 0; i < 8; i++)
            cpa16(sA[s] + (lrow + i * 16) * 128 + ssw, Ag + kof + (size_t)i * 16 * KK);
        #pragma unroll
        for (int i = 0; i < 8; i++)
            cpa16(sB[s] + (lrow + i * 16) * 128 + ssw, Bg + kof + (size_t)i * 16 * KK);
    };

    float acc[4][8][4];
    #pragma unroll
    for (int i = 0; i < 4; i++)
        #pragma unroll
        for (int j = 0; j < 8; j++)
            #pragma unroll
            for (int r = 0; r < 4; r++) acc[i][j][r] = 0.f;

    load_stage(0, 0); CP_COMMIT();
    load_stage(1, 1); CP_COMMIT();

    const uint32_t maskx = (lane & 7) << 4;
    const uint32_t aRow = (wm * 64 + (lane & 15)) * 128;
    const uint32_t bRow = (wn * 64 + (lane & 7) + ((lane >> 4) & 1) * 8) * 128;
    uint32_t axo[4], bxo[4];
    {
        const uint32_t aHf = (lane >> 4) * 16;
        const uint32_t bHf = ((lane >> 3) & 1) * 16;
        #pragma unroll
        for (int kh = 0; kh < 4; kh++) {
            axo[kh] = (kh * 32 + aHf) ^ maskx;
            bxo[kh] = (kh * 32 + bHf) ^ maskx;
        }
    }

    uint32_t af[2][4][4], bf[2][8][2];

    #define LD_FRAGS(buf, sAd, sBd, kh) do {                                   \
        _Pragma("unroll")                                                      \
        for (int mt = 0; mt < 4; mt++)                                         \
            LDSM4(af[buf][mt][0], af[buf][mt][1], af[buf][mt][2],              \
                  af[buf][mt][3], (sAd) + aRow + mt * 16 * 128 + axo[kh]);     \
        _Pragma("unroll")                                                      \
        for (int np = 0; np < 4; np++)                                         \
            LDSM4(bf[buf][np*2][0], bf[buf][np*2][1], bf[buf][np*2+1][0],      \
                  bf[buf][np*2+1][1], (sBd) + bRow + np * 16 * 128 + bxo[kh]); \
    } while (0)

    #define MMA_BLOCK(buf) do {                                                \
        _Pragma("unroll")                                                      \
        for (int mt = 0; mt < 4; mt++)                                         \
            _Pragma("unroll")                                                  \
            for (int nt = 0; nt < 8; nt++)                                     \
                MMA16816(acc[mt][nt], af[buf][mt], bf[buf][nt]);               \
    } while (0)

    CP_WAIT1();
    __syncthreads();
    LD_FRAGS(0, sA[0], sB[0], 0);

    for (int kt = 0; kt < NT; kt++) {
        const int s  = kt % 3;
        const int sn = (kt + 1) % 3;
        const uint32_t sAd = sA[s], sBd = sB[s];

        LD_FRAGS(1, sAd, sBd, 1);
        MMA_BLOCK(0);
        LD_FRAGS(0, sAd, sBd, 2);
        MMA_BLOCK(1);
        LD_FRAGS(1, sAd, sBd, 3);
        MMA_BLOCK(0);

        if (kt + 1 < NT) {
            CP_WAIT1();
            __syncthreads();
            if (kt + 2 < NT) load_stage((kt + 2) % 3, kt + 2);
            CP_COMMIT();
            LD_FRAGS(0, sA[sn], sB[sn], 0);
        }
        MMA_BLOCK(1);
    }

    float bv0[8], bv1[8];
    #pragma unroll
    for (int nt = 0; nt < 8; nt++) {
        int col = bx * 128 + wn * 64 + nt * 8 + (lane & 3) * 2;
        bv0[nt] = __ldg(bias + col);
        bv1[nt] = __ldg(bias + col + 1);
    }
    #pragma unroll
    for (int mt = 0; mt < 4; mt++) {
        int r0 = by * 128 + wm * 64 + mt * 16 + (lane >> 2);
        #pragma unroll
        for (int nt = 0; nt < 8; nt++) {
            int col = bx * 128 + wn * 64 + nt * 8 + (lane & 3) * 2;
            float v0 = acc[mt][nt][0] + bv0[nt], v1 = acc[mt][nt][1] + bv1[nt];
            float v2 = acc[mt][nt][2] + bv0[nt], v3 = acc[mt][nt][3] + bv1[nt];
            if (epi == 1) { v0 = gelu_exact(v0); v1 = gelu_exact(v1);
                            v2 = gelu_exact(v2); v3 = gelu_exact(v3); }
            if (epi == 2) {
                __half* Ch = (__half*)Cv;
                *(__half2*)(Ch + (size_t)r0 * ldc + col) =
                    __halves2half2(__float2half(v0), __float2half(v1));
                *(__half2*)(Ch + (size_t)(r0 + 8) * ldc + col) =
                    __halves2half2(__float2half(v2), __float2half(v3));
            } else {
                float* C = (float*)Cv;
                *(float2*)(C + (size_t)r0 * ldc + col)       = make_float2(v0, v1);
                *(float2*)(C + (size_t)(r0 + 8) * ldc + col) = make_float2(v2, v3);
            }
        }
    }
    #undef LD_FRAGS
    #undef MMA_BLOCK
}

// ---------------- windowed local attention, smem-tiled -----------------------
// block = 256 threads: 16 rows x 1 head-quad. Rows [r0-2, r0+18) of the quad's
// q/k/v slices staged in smem (zero-padded at batch-segment bounds).
// 8 warps compute 2 rows each; numerics identical to the register version.
#define AT_ROWS 16
#define AT_SPAN (AT_ROWS + 4)        // 20 staged rows

__global__ void attn_kernel(const __half* __restrict__ qkv,
                            __half* __restrict__ out)
{
    __shared__ __half sq[AT_SPAN][256];
    __shared__ __half sk[AT_SPAN][256];
    __shared__ __half sv[AT_SPAN][256];

    const int tid  = threadIdx.x;
    const int quad = blockIdx.x & 3;
    const int rb   = blockIdx.x >> 2;           // row-block 0..511
    const int r0   = rb * AT_ROWS;
    const int seg  = r0 & ~(TT - 1);            // batch segment base

    // ---- load phase: 20 rows x 3 parts x 32 uint4 = 1920 uint4 ----
    for (int idx = tid; idx < AT_SPAN * 3 * 32; idx += 256) {
        int u     = idx & 31;
        int slice = idx >> 5;                   // 0..59
        int i     = slice / 3;                  // staged row 0..19
        int part  = slice - i * 3;
        int g     = r0 - 2 + i;
        uint4 val = make_uint4(0, 0, 0, 0);
        if (g >= seg && g < seg + TT)
            val = *(const uint4*)(qkv + (size_t)g * (3 * DIM) + part * DIM
                                  + quad * 256 + u * 8);
        __half* dst = (part == 0) ? &sq[i][u * 8]
                     : (part == 1) ? &sk[i][u * 8] : &sv[i][u * 8];
        *(uint4*)dst = val;
    }
    __syncthreads();

    const int wid  = tid >> 5;
    const int lane = tid & 31;
    const int loff = lane * 8;                  // dim offset within quad

    auto dot8 = [&](const __half* a, const __half* b) -> float {
        float d = 0.f;
        const __half2* ah = (const __half2*)a;
        const __half2* bh = (const __half2*)b;
        #pragma unroll
        for (int j = 0; j < 4; j++) {
            float2 fa = __half22float2(ah[j]);
            float2 fb = __half22float2(bh[j]);
            d += fa.x * fb.x + fa.y * fb.y;
        }
        return d;
    };
    auto wsum_st = [&](__half* dst, const __half* p0, const __half* p1,
                       const __half* p2, float e0, float e1, float e2) {
        uint4 o;
        __half2* po = (__half2*)&o;
        const __half2* h0 = (const __half2*)p0;
        const __half2* h1 = (const __half2*)p1;
        const __half2* h2 = (const __half2*)p2;
        #pragma unroll
        for (int j = 0; j < 4; j++) {
            float2 f0 = __half22float2(h0[j]);
            float2 f1 = __half22float2(h1[j]);
            float2 f2 = __half22float2(h2[j]);
            float a = e0 * f0.x + e1 * f1.x + e2 * f2.x;
            float b = e0 * f0.y + e1 * f1.y + e2 * f2.y;
            po[j] = __halves2half2(__float2half(a), __float2half(b));
        }
        *(uint4*)dst = o;
    };

    #pragma unroll
    for (int rr = 0; rr < 2; rr++) {
        const int lr  = wid * 2 + rr;           // local row 0..15
        const int i   = lr + 2;                 // staged index
        const int row = r0 + lr;
        __half* orow = out + (size_t)row * (2 * DIM) + quad * 256 + loff;

        {   // forward: q[i-1]; k,v at i, i-1, i-2
            float d0 = dot8(&sq[i-1][loff], &sk[i  ][loff]);
            float d1 = dot8(&sq[i-1][loff], &sk[i-1][loff]);
            float d2 = dot8(&sq[i-1][loff], &sk[i-2][loff]);
            #pragma unroll
            for (int o = 4; o; o >>= 1) {
                d0 += __shfl_xor_sync(0xffffffffu, d0, o);
                d1 += __shfl_xor_sync(0xffffffffu, d1, o);
                d2 += __shfl_xor_sync(0xffffffffu, d2, o);
            }
            d0 *= 0.125f; d1 *= 0.125f; d2 *= 0.125f;
            float m = fmaxf(d0, fmaxf(d1, d2));
            float e0 = expf(d0-m), e1 = expf(d1-m), e2 = expf(d2-m);
            float inv = 1.0f / (e0 + e1 + e2);
            wsum_st(orow, &sv[i][loff], &sv[i-1][loff], &sv[i-2][loff],
                    e0 * inv, e1 * inv, e2 * inv);
        }
        {   // reverse: q[i+1]; k,v at i, i+1, i+2
            float d0 = dot8(&sq[i+1][loff], &sk[i  ][loff]);
            float d1 = dot8(&sq[i+1][loff], &sk[i+1][loff]);
            float d2 = dot8(&sq[i+1][loff], &sk[i+2][loff]);
            #pragma unroll
            for (int o = 4; o; o >>= 1) {
                d0 += __shfl_xor_sync(0xffffffffu, d0, o);
                d1 += __shfl_xor_sync(0xffffffffu, d1, o);
                d2 += __shfl_xor_sync(0xffffffffu, d2, o);
            }
            d0 *= 0.125f; d1 *= 0.125f; d2 *= 0.125f;
            float m = fmaxf(d0, fmaxf(d1, d2));
            float e0 = expf(d0-m), e1 = expf(d1-m), e2 = expf(d2-m);
            float inv = 1.0f / (e0 + e1 + e2);
            wsum_st(orow + DIM, &sv[i][loff], &sv[i+1][loff], &sv[i+2][loff],
                    e0 * inv, e1 * inv, e2 * inv);
        }
    }
}

// ---------------- launch ----------------------------------------------------
extern "C" void kernel_launch(void* const* d_in, const int* in_sizes, int n_in,
                              void* d_out, int out_size)
{
    const float* x   = (const float*)d_in[0];
    const float* Wq  = (const float*)d_in[1];
    const float* bq  = (const float*)d_in[2];
    const float* Wk  = (const float*)d_in[3];
    const float* bk  = (const float*)d_in[4];
    const float* Wv  = (const float*)d_in[5];
    const float* bv  = (const float*)d_in[6];
    const float* Wfb = (const float*)d_in[7];
    const float* bfb = (const float*)d_in[8];
    const float* Wo  = (const float*)d_in[9];
    const float* bo  = (const float*)d_in[10];
    const float* g1  = (const float*)d_in[11];
    const float* b1  = (const float*)d_in[12];
    const float* g2  = (const float*)d_in[13];
    const float* b2  = (const float*)d_in[14];
    float* out = (float*)d_out;

    void *p;
    float *bqkv;
    __half *xh, *qkv, *at, *yh, *zh, *wqkvT, *woT, *wfbT;
    cudaGetSymbolAddress(&p, g_bqkv);  bqkv  = (float*)p;
    cudaGetSymbolAddress(&p, g_xh);    xh    = (__half*)p;
    cudaGetSymbolAddress(&p, g_qkv);   qkv   = (__half*)p;
    cudaGetSymbolAddress(&p, g_at);    at    = (__half*)p;
    cudaGetSymbolAddress(&p, g_yh);    yh    = (__half*)p;
    cudaGetSymbolAddress(&p, g_zh);    zh    = (__half*)p;
    cudaGetSymbolAddress(&p, g_wqkvT); wqkvT = (__half*)p;
    cudaGetSymbolAddress(&p, g_woT);   woT   = (__half*)p;
    cudaGetSymbolAddress(&p, g_wfbT);  wfbT  = (__half*)p;

    cudaFuncSetAttribute(gemm_hmma<1>, cudaFuncAttributeMaxDynamicSharedMemorySize, GSMEM);
    cudaFuncSetAttribute(gemm_hmma<0>, cudaFuncAttributeMaxDynamicSharedMemorySize, GSMEM);

    // 0) prep: LN1 + wqkv transpose + bias concat
    prep_kernel<<<MROWS + WQKV_TILES + BBLOCKS, 256>>>(
        x, g1, b1, xh, Wq, Wk, Wv, bq, bk, bv, bqkv);

    // 1) fused qkv GEMM (1536 tiles) + tail aux: Wo/Wfb transposes
    gemm_hmma<1><<<1536 + AUX_TOT, 128, GSMEM>>>(
        xh, wqkvT, bqkv, qkv, DIM, 3*DIM, 2, 1536, 24, Wo, Wfb);

    // 2) local attention (smem-tiled): 512 row-blocks x 4 quads
    attn_kernel<<<(MROWS / AT_ROWS) * 4, 256>>>(qkv, at);

    // 3) y = at @ Wfb + bfb, K=2048, fp16 out
    gemm_hmma<0><<<512, 128, GSMEM>>>(at, wfbT, bfb, yh, 2*DIM, DIM, 2, 512, 8,
                                      nullptr, nullptr);
    // 4) LN2(y + xh) -> fp16
    ln2_kernel<<<MROWS, 256>>>(yh, xh, g2, b2, zh);
    // 5) out = gelu(z @ Wo + bo), K=1024, fp32+gelu
    gemm_hmma<0><<<512, 128, GSMEM>>>(zh, woT, bo, out, DIM, DIM, 1, 512, 8,
                                      nullptr, nullptr);
}

// round 16
// speedup vs baseline: 1.0317x; 1.0317x over previous
#include <cuda_runtime.h>
#include <cuda_fp16.h>
#include <math.h>
#include <stdint.h>

// Problem constants
#define BATCH 2
#define TT    4096
#define DIM   1024
#define MROWS (BATCH * TT)     // 8192
#define HEADS 16
#define HS    64

// ---------------- scratch (static device globals; no allocation) ------------
__device__ __half g_xh  [(size_t)MROWS * DIM];          // LN1 out (GEMM A + residual)
__device__ __half g_qkv [(size_t)MROWS * 3 * DIM];      // [q|k|v] fp16
__device__ __half g_at  [(size_t)MROWS * 2 * DIM];      // attn out fp16
__device__ __half g_yh  [(size_t)MROWS * DIM];          // fb out fp16
__device__ __half g_zh  [(size_t)MROWS * DIM];          // LN2 out fp16
__device__ __half g_wqkvT[(size_t)(3 * DIM) * DIM];     // 3072 x 1024 (N-major)
__device__ __half g_woT [(size_t)DIM * DIM];            // 1024 x 1024
__device__ __half g_wfbT[(size_t)DIM * 2 * DIM];        // 1024 x 2048
__device__ float g_bqkv[3 * DIM];

// ---------------- PTX helpers ----------------------------------------------
__device__ __forceinline__ uint32_t s2u(const void* p) {
    uint32_t a;
    asm("{ .reg .u64 t; cvta.to.shared.u64 t, %1; cvt.u32.u64 %0, t; }"
        : "=r"(a) : "l"(p));
    return a;
}
__device__ __forceinline__ void cpa16(uint32_t s, const void* g) {
    asm volatile("cp.async.cg.shared.global [%0], [%1], 16;" :: "r"(s), "l"(g));
}
#define CP_COMMIT() asm volatile("cp.async.commit_group;" ::: "memory")
#define CP_WAIT1()  asm volatile("cp.async.wait_group 1;" ::: "memory")

#define LDSM4(r0, r1, r2, r3, addr) \
    asm volatile("ldmatrix.sync.aligned.m8n8.x4.shared.b16 {%0,%1,%2,%3}, [%4];" \
        : "=r"(r0), "=r"(r1), "=r"(r2), "=r"(r3) : "r"(addr))

#define MMA16816(d, a, b) \
    asm volatile("mma.sync.aligned.m16n8k16.row.col.f32.f16.f16.f32 " \
        "{%0,%1,%2,%3},{%4,%5,%6,%7},{%8,%9},{%0,%1,%2,%3};" \
        : "+f"((d)[0]), "+f"((d)[1]), "+f"((d)[2]), "+f"((d)[3]) \
        : "r"((a)[0]), "r"((a)[1]), "r"((a)[2]), "r"((a)[3]), \
          "r"((b)[0]), "r"((b)[1]))

// ---------------- prep: LN1 + wqkv transpose + bias concat ------------------
#define WQKV_TILES 3072             // Wq, Wk, Wv: 3 x 1024 32x32 tiles
#define BBLOCKS 12                  // 3072 / 256

__global__ void prep_kernel(const float* __restrict__ x,
                            const float* __restrict__ g1,
                            const float* __restrict__ b1,
                            __half* __restrict__ xh,
                            const float* __restrict__ Wq,
                            const float* __restrict__ Wk,
                            const float* __restrict__ Wv,
                            const float* __restrict__ bq,
                            const float* __restrict__ bk,
                            const float* __restrict__ bv,
                            float* __restrict__ bqkv)
{
    __shared__ float rs[8], rss[8];
    __shared__ float ts[32][33];
    int blk = blockIdx.x;
    int tid = threadIdx.x;

    if (blk < MROWS) {
        int row = blk;
        float4 v = ((const float4*)(x + (size_t)row * DIM))[tid];
        float s  = v.x + v.y + v.z + v.w;
        float ss = v.x*v.x + v.y*v.y + v.z*v.z + v.w*v.w;
        #pragma unroll
        for (int o = 16; o; o >>= 1) {
            s  += __shfl_xor_sync(0xffffffffu, s,  o);
            ss += __shfl_xor_sync(0xffffffffu, ss, o);
        }
        int wid = tid >> 5, lid = tid & 31;
        if (lid == 0) { rs[wid] = s; rss[wid] = ss; }
        __syncthreads();
        float tots = 0.f, totss = 0.f;
        #pragma unroll
        for (int i = 0; i < 8; i++) { tots += rs[i]; totss += rss[i]; }
        float mean = tots * (1.0f / DIM);
        float var  = totss * (1.0f / DIM) - mean * mean;
        float inv  = rsqrtf(var + 1e-6f);
        float4 gg = ((const float4*)g1)[tid], bb = ((const float4*)b1)[tid];
        float ox = (v.x - mean) * inv * gg.x + bb.x;
        float oy = (v.y - mean) * inv * gg.y + bb.y;
        float oz = (v.z - mean) * inv * gg.z + bb.z;
        float ow = (v.w - mean) * inv * gg.w + bb.w;
        __half* base = xh + (size_t)row * DIM + tid * 4;
        *(__half2*)(base)     = __halves2half2(__float2half(ox), __float2half(oy));
        *(__half2*)(base + 2) = __halves2half2(__float2half(oz), __float2half(ow));
        return;
    }
    blk -= MROWS;
    if (blk < WQKV_TILES) {
        int which = blk >> 10;
        int tile  = blk & 1023;
        const float* W = (which == 0) ? Wq : (which == 1) ? Wk : Wv;
        int nofs = which * DIM;
        int k0 = (tile >> 5) * 32;
        int n0 = (tile & 31) * 32;
        int r = tid >> 5, c = tid & 31;
        #pragma unroll
        for (int i = 0; i < 4; i++)
            ts[r + 8 * i][c] = W[(size_t)(k0 + r + 8 * i) * DIM + n0 + c];
        __syncthreads();
        #pragma unroll
        for (int i = 0; i < 4; i++) {
            int n = n0 + r + 8 * i;
            g_wqkvT[(size_t)(nofs + n) * DIM + k0 + c] = __float2half(ts[c][r + 8 * i]);
        }
        return;
    }
    blk -= WQKV_TILES;
    int i = blk * 256 + tid;
    if (i < DIM) bqkv[i] = bq[i];
    else if (i < 2 * DIM) bqkv[i] = bk[i - DIM];
    else if (i < 3 * DIM) bqkv[i] = bv[i - 2 * DIM];
}

// ---------------- LN2: fp16 y + fp16 residual -> fp16 out -------------------
__global__ void ln2_kernel(const __half* __restrict__ y,
                           const __half* __restrict__ res,
                           const float* __restrict__ g,
                           const float* __restrict__ b,
                           __half* __restrict__ h_out)
{
    __shared__ float rs[8], rss[8];
    int row = blockIdx.x;
    int tid = threadIdx.x;
    uint2 uy = ((const uint2*)(y   + (size_t)row * DIM))[tid];
    uint2 ur = ((const uint2*)(res + (size_t)row * DIM))[tid];
    float2 y0 = __half22float2(*(__half2*)&uy.x);
    float2 y1 = __half22float2(*(__half2*)&uy.y);
    float2 r0 = __half22float2(*(__half2*)&ur.x);
    float2 r1 = __half22float2(*(__half2*)&ur.y);
    float4 v = make_float4(y0.x + r0.x, y0.y + r0.y, y1.x + r1.x, y1.y + r1.y);
    float s  = v.x + v.y + v.z + v.w;
    float ss = v.x*v.x + v.y*v.y + v.z*v.z + v.w*v.w;
    #pragma unroll
    for (int o = 16; o; o >>= 1) {
        s  += __shfl_xor_sync(0xffffffffu, s,  o);
        ss += __shfl_xor_sync(0xffffffffu, ss, o);
    }
    int wid = tid >> 5, lid = tid & 31;
    if (lid == 0) { rs[wid] = s; rss[wid] = ss; }
    __syncthreads();
    float tots = 0.f, totss = 0.f;
    #pragma unroll
    for (int i = 0; i < 8; i++) { tots += rs[i]; totss += rss[i]; }
    float mean = tots * (1.0f / DIM);
    float var  = totss * (1.0f / DIM) - mean * mean;
    float inv  = rsqrtf(var + 1e-6f);
    float4 gg = ((const float4*)g)[tid], bb = ((const float4*)b)[tid];
    float ox = (v.x - mean) * inv * gg.x + bb.x;
    float oy = (v.y - mean) * inv * gg.y + bb.y;
    float oz = (v.z - mean) * inv * gg.z + bb.z;
    float ow = (v.w - mean) * inv * gg.w + bb.w;
    __half* base = h_out + (size_t)row * DIM + tid * 4;
    *(__half2*)(base)     = __halves2half2(__float2half(ox), __float2half(oy));
    *(__half2*)(base + 2) = __halves2half2(__float2half(oz), __float2half(ow));
}

// ---------------- HMMA fp16 GEMM (templated: AUX tail transposes) -----------
#define STG_OP 16384
#define GSMEM  (3 * 2 * STG_OP)      // 98304
#define AUX_WO   1024
#define AUX_WFB  2048
#define AUX_TOT  (AUX_WO + AUX_WFB)  // 3072

__device__ __forceinline__ float gelu_exact(float x) {
    return 0.5f * x * (1.0f + erff(x * 0.7071067811865475f));
}

template<int AUX>
__global__ __launch_bounds__(128, 2)
void gemm_hmma(const __half* __restrict__ A, const __half* __restrict__ B,
               const float* __restrict__ bias, void* __restrict__ Cv,
               int KK, int ldc, int epi, int ntiles, int nx,
               const float* __restrict__ WoSrc, const float* __restrict__ WfbSrc)
{
    extern __shared__ char smem[];
    const int bid = blockIdx.x;
    const int tid = threadIdx.x;

    if (AUX && bid >= ntiles) {
        // ---- aux: coalesced 32x32 transpose (128 threads, 4 rows/pass) ----
        float (*ts)[33] = (float(*)[33])smem;
        int blk = bid - ntiles;
        const float* W; __half* O; int K, tile;
        if (blk < AUX_WO) { W = WoSrc; O = g_woT; K = DIM; tile = blk; }
        else { W = WfbSrc; O = g_wfbT; K = 2 * DIM; tile = blk - AUX_WO; }
        int k0 = (tile >> 5) * 32;
        int n0 = (tile & 31) * 32;
        int r = tid >> 5, c = tid & 31;
        #pragma unroll
        for (int i = 0; i < 8; i++)
            ts[r + 4 * i][c] = W[(size_t)(k0 + r + 4 * i) * DIM + n0 + c];
        __syncthreads();
        #pragma unroll
        for (int i = 0; i < 8; i++) {
            int n = n0 + r + 4 * i;
            O[(size_t)n * K + k0 + c] = __float2half(ts[c][r + 4 * i]);
        }
        return;
    }

    const uint32_t sb = s2u(smem);
    const int wid  = tid >> 5, lane = tid & 31;
    const int bx   = bid % nx, by = bid / nx;
    const int wm   = wid & 1;
    const int wn   = wid >> 1;
    const int NT   = KK >> 6;

    uint32_t sA[3], sB[3];
    #pragma unroll
    for (int s = 0; s < 3; s++) {
        sA[s] = sb + s * 2 * STG_OP;
        sB[s] = sA[s] + STG_OP;
    }

    const int lrow = tid >> 3;
    const uint32_t ssw = ((tid & 7) * 16) ^ ((lrow & 7) << 4);
    const __half* Ag = A + (size_t)(by * 128 + lrow) * KK + (tid & 7) * 8;
    const __half* Bg = B + (size_t)(bx * 128 + lrow) * KK + (tid & 7) * 8;

    auto load_stage = [&](int s, int kt) {
        size_t kof = (size_t)kt * 64;
        #pragma unroll
        for (int i = 0; i < 8; i++)
            cpa16(sA[s] + (lrow + i * 16) * 128 + ssw, Ag + kof + (size_t)i * 16 * KK);
        #pragma unroll
        for (int i = 0; i < 8; i++)
            cpa16(sB[s] + (lrow + i * 16) * 128 + ssw, Bg + kof + (size_t)i * 16 * KK);
    };

    float acc[4][8][4];
    #pragma unroll
    for (int i = 0; i < 4; i++)
        #pragma unroll
        for (int j = 0; j < 8; j++)
            #pragma unroll
            for (int r = 0; r < 4; r++) acc[i][j][r] = 0.f;

    load_stage(0, 0); CP_COMMIT();
    load_stage(1, 1); CP_COMMIT();

    const uint32_t maskx = (lane & 7) << 4;
    const uint32_t aRow = (wm * 64 + (lane & 15)) * 128;
    const uint32_t bRow = (wn * 64 + (lane & 7) + ((lane >> 4) & 1) * 8) * 128;
    uint32_t axo[4], bxo[4];
    {
        const uint32_t aHf = (lane >> 4) * 16;
        const uint32_t bHf = ((lane >> 3) & 1) * 16;
        #pragma unroll
        for (int kh = 0; kh < 4; kh++) {
            axo[kh] = (kh * 32 + aHf) ^ maskx;
            bxo[kh] = (kh * 32 + bHf) ^ maskx;
        }
    }

    uint32_t af[2][4][4], bf[2][8][2];

    #define LD_FRAGS(buf, sAd, sBd, kh) do {                                   \
        _Pragma("unroll")                                                      \
        for (int mt = 0; mt < 4; mt++)                                         \
            LDSM4(af[buf][mt][0], af[buf][mt][1], af[buf][mt][2],              \
                  af[buf][mt][3], (sAd) + aRow + mt * 16 * 128 + axo[kh]);     \
        _Pragma("unroll")                                                      \
        for (int np = 0; np < 4; np++)                                         \
            LDSM4(bf[buf][np*2][0], bf[buf][np*2][1], bf[buf][np*2+1][0],      \
                  bf[buf][np*2+1][1], (sBd) + bRow + np * 16 * 128 + bxo[kh]); \
    } while (0)

    #define MMA_BLOCK(buf) do {                                                \
        _Pragma("unroll")                                                      \
        for (int mt = 0; mt < 4; mt++)                                         \
            _Pragma("unroll")                                                  \
            for (int nt = 0; nt < 8; nt++)                                     \
                MMA16816(acc[mt][nt], af[buf][mt], bf[buf][nt]);               \
    } while (0)

    CP_WAIT1();
    __syncthreads();
    LD_FRAGS(0, sA[0], sB[0], 0);

    for (int kt = 0; kt < NT; kt++) {
        const int s  = kt % 3;
        const int sn = (kt + 1) % 3;
        const uint32_t sAd = sA[s], sBd = sB[s];

        LD_FRAGS(1, sAd, sBd, 1);
        MMA_BLOCK(0);
        LD_FRAGS(0, sAd, sBd, 2);
        MMA_BLOCK(1);
        LD_FRAGS(1, sAd, sBd, 3);
        MMA_BLOCK(0);

        if (kt + 1 < NT) {
            CP_WAIT1();
            __syncthreads();
            if (kt + 2 < NT) load_stage((kt + 2) % 3, kt + 2);
            CP_COMMIT();
            LD_FRAGS(0, sA[sn], sB[sn], 0);
        }
        MMA_BLOCK(1);
    }

    float bv0[8], bv1[8];
    #pragma unroll
    for (int nt = 0; nt < 8; nt++) {
        int col = bx * 128 + wn * 64 + nt * 8 + (lane & 3) * 2;
        bv0[nt] = __ldg(bias + col);
        bv1[nt] = __ldg(bias + col + 1);
    }
    #pragma unroll
    for (int mt = 0; mt < 4; mt++) {
        int r0 = by * 128 + wm * 64 + mt * 16 + (lane >> 2);
        #pragma unroll
        for (int nt = 0; nt < 8; nt++) {
            int col = bx * 128 + wn * 64 + nt * 8 + (lane & 3) * 2;
            float v0 = acc[mt][nt][0] + bv0[nt], v1 = acc[mt][nt][1] + bv1[nt];
            float v2 = acc[mt][nt][2] + bv0[nt], v3 = acc[mt][nt][3] + bv1[nt];
            if (epi == 1) { v0 = gelu_exact(v0); v1 = gelu_exact(v1);
                            v2 = gelu_exact(v2); v3 = gelu_exact(v3); }
            if (epi == 2) {
                __half* Ch = (__half*)Cv;
                *(__half2*)(Ch + (size_t)r0 * ldc + col) =
                    __halves2half2(__float2half(v0), __float2half(v1));
                *(__half2*)(Ch + (size_t)(r0 + 8) * ldc + col) =
                    __halves2half2(__float2half(v2), __float2half(v3));
            } else {
                float* C = (float*)Cv;
                *(float2*)(C + (size_t)r0 * ldc + col)       = make_float2(v0, v1);
                *(float2*)(C + (size_t)(r0 + 8) * ldc + col) = make_float2(v2, v3);
            }
        }
    }
    #undef LD_FRAGS
    #undef MMA_BLOCK
}

// ---------------- windowed local attention (round-14 register version) ------
// warp = (row, 4 heads): 8 lanes per head, each lane owns 8 dims (uint4 = 16B).
__global__ void attn_kernel(const __half* __restrict__ qkv,
                            __half* __restrict__ out)
{
    int gw   = (blockIdx.x * blockDim.x + threadIdx.x) >> 5;
    int lane = threadIdx.x & 31;
    if (gw >= MROWS * (HEADS / 4)) return;
    int quad = gw & 3;
    int row  = gw >> 2;
    int t    = row & (TT - 1);
    int off = quad * 256 + (lane >> 3) * 64 + (lane & 7) * 8;

    auto ld8 = [&](int part, int rr) -> uint4 {
        return *(const uint4*)(qkv + (size_t)rr * (3 * DIM) + part * DIM + off);
    };
    auto dot8 = [](uint4 a, uint4 b) -> float {
        float d = 0.f;
        const __half2* ah = (const __half2*)&a;
        const __half2* bh = (const __half2*)&b;
        #pragma unroll
        for (int j = 0; j < 4; j++) {
            float2 fa = __half22float2(ah[j]);
            float2 fb = __half22float2(bh[j]);
            d += fa.x * fb.x + fa.y * fb.y;
        }
        return d;
    };
    auto wsum = [](uint4 v0, uint4 v1, uint4 v2,
                   float e0, float e1, float e2) -> uint4 {
        uint4 o;
        const __half2* p0 = (const __half2*)&v0;
        const __half2* p1 = (const __half2*)&v1;
        const __half2* p2 = (const __half2*)&v2;
        __half2* po = (__half2*)&o;
        #pragma unroll
        for (int j = 0; j < 4; j++) {
            float2 f0 = __half22float2(p0[j]);
            float2 f1 = __half22float2(p1[j]);
            float2 f2 = __half22float2(p2[j]);
            float a = e0 * f0.x + e1 * f1.x + e2 * f2.x;
            float b = e0 * f0.y + e1 * f1.y + e2 * f2.y;
            po[j] = __halves2half2(__float2half(a), __float2half(b));
        }
        return o;
    };
    const uint4 zero = make_uint4(0, 0, 0, 0);

    uint4 k0 = ld8(1, row);
    uint4 v0 = ld8(2, row);

    {   // forward: query = q[t-1], keys/values rows t, t-1, t-2
        uint4 qf = (t >= 1) ? ld8(0, row - 1) : zero;
        uint4 k1 = (t >= 1) ? ld8(1, row - 1) : zero;
        uint4 k2 = (t >= 2) ? ld8(1, row - 2) : zero;
        float d0 = dot8(qf, k0), d1 = dot8(qf, k1), d2 = dot8(qf, k2);
        #pragma unroll
        for (int o = 4; o; o >>= 1) {
            d0 += __shfl_xor_sync(0xffffffffu, d0, o);
            d1 += __shfl_xor_sync(0xffffffffu, d1, o);
            d2 += __shfl_xor_sync(0xffffffffu, d2, o);
        }
        d0 *= 0.125f; d1 *= 0.125f; d2 *= 0.125f;
        float m = fmaxf(d0, fmaxf(d1, d2));
        float e0 = expf(d0-m), e1 = expf(d1-m), e2 = expf(d2-m);
        float inv = 1.0f / (e0 + e1 + e2);
        e0 *= inv; e1 *= inv; e2 *= inv;
        uint4 v1 = (t >= 1) ? ld8(2, row - 1) : zero;
        uint4 v2 = (t >= 2) ? ld8(2, row - 2) : zero;
        *(uint4*)(out + (size_t)row * (2 * DIM) + off) = wsum(v0, v1, v2, e0, e1, e2);
    }
    {   // reverse: query = q[t+1], keys/values rows t, t+1, t+2
        uint4 qr = (t + 1 < TT) ? ld8(0, row + 1) : zero;
        uint4 k1 = (t + 1 < TT) ? ld8(1, row + 1) : zero;
        uint4 k2 = (t + 2 < TT) ? ld8(1, row + 2) : zero;
        float d0 = dot8(qr, k0), d1 = dot8(qr, k1), d2 = dot8(qr, k2);
        #pragma unroll
        for (int o = 4; o; o >>= 1) {
            d0 += __shfl_xor_sync(0xffffffffu, d0, o);
            d1 += __shfl_xor_sync(0xffffffffu, d1, o);
            d2 += __shfl_xor_sync(0xffffffffu, d2, o);
        }
        d0 *= 0.125f; d1 *= 0.125f; d2 *= 0.125f;
        float m = fmaxf(d0, fmaxf(d1, d2));
        float e0 = expf(d0-m), e1 = expf(d1-m), e2 = expf(d2-m);
        float inv = 1.0f / (e0 + e1 + e2);
        e0 *= inv; e1 *= inv; e2 *= inv;
        uint4 v1 = (t + 1 < TT) ? ld8(2, row + 1) : zero;
        uint4 v2 = (t + 2 < TT) ? ld8(2, row + 2) : zero;
        *(uint4*)(out + (size_t)row * (2 * DIM) + DIM + off) = wsum(v0, v1, v2, e0, e1, e2);
    }
}

// ---------------- launch ----------------------------------------------------
extern "C" void kernel_launch(void* const* d_in, const int* in_sizes, int n_in,
                              void* d_out, int out_size)
{
    const float* x   = (const float*)d_in[0];
    const float* Wq  = (const float*)d_in[1];
    const float* bq  = (const float*)d_in[2];
    const float* Wk  = (const float*)d_in[3];
    const float* bk  = (const float*)d_in[4];
    const float* Wv  = (const float*)d_in[5];
    const float* bv  = (const float*)d_in[6];
    const float* Wfb = (const float*)d_in[7];
    const float* bfb = (const float*)d_in[8];
    const float* Wo  = (const float*)d_in[9];
    const float* bo  = (const float*)d_in[10];
    const float* g1  = (const float*)d_in[11];
    const float* b1  = (const float*)d_in[12];
    const float* g2  = (const float*)d_in[13];
    const float* b2  = (const float*)d_in[14];
    float* out = (float*)d_out;

    void *p;
    float *bqkv;
    __half *xh, *qkv, *at, *yh, *zh, *wqkvT, *woT, *wfbT;
    cudaGetSymbolAddress(&p, g_bqkv);  bqkv  = (float*)p;
    cudaGetSymbolAddress(&p, g_xh);    xh    = (__half*)p;
    cudaGetSymbolAddress(&p, g_qkv);   qkv   = (__half*)p;
    cudaGetSymbolAddress(&p, g_at);    at    = (__half*)p;
    cudaGetSymbolAddress(&p, g_yh);    yh    = (__half*)p;
    cudaGetSymbolAddress(&p, g_zh);    zh    = (__half*)p;
    cudaGetSymbolAddress(&p, g_wqkvT); wqkvT = (__half*)p;
    cudaGetSymbolAddress(&p, g_woT);   woT   = (__half*)p;
    cudaGetSymbolAddress(&p, g_wfbT);  wfbT  = (__half*)p;

    cudaFuncSetAttribute(gemm_hmma<1>, cudaFuncAttributeMaxDynamicSharedMemorySize, GSMEM);
    cudaFuncSetAttribute(gemm_hmma<0>, cudaFuncAttributeMaxDynamicSharedMemorySize, GSMEM);

    // 0) prep: LN1 + wqkv transpose + bias concat
    prep_kernel<<<MROWS + WQKV_TILES + BBLOCKS, 256>>>(
        x, g1, b1, xh, Wq, Wk, Wv, bq, bk, bv, bqkv);

    // 1) fused qkv GEMM (1536 tiles) + tail aux: Wo/Wfb transposes
    gemm_hmma<1><<<1536 + AUX_TOT, 128, GSMEM>>>(
        xh, wqkvT, bqkv, qkv, DIM, 3*DIM, 2, 1536, 24, Wo, Wfb);

    // 2) local attention (register version), warp = 4 heads
    attn_kernel<<<(MROWS*(HEADS/4)*32)/256, 256>>>(qkv, at);

    // 3) y = at @ Wfb + bfb, K=2048, fp16 out
    gemm_hmma<0><<<512, 128, GSMEM>>>(at, wfbT, bfb, yh, 2*DIM, DIM, 2, 512, 8,
                                      nullptr, nullptr);
    // 4) LN2(y + xh) -> fp16
    ln2_kernel<<<MROWS, 256>>>(yh, xh, g2, b2, zh);
    // 5) out = gelu(z @ Wo + bo), K=1024, fp32+gelu
    gemm_hmma<0><<<512, 128, GSMEM>>>(zh, woT, bo, out, DIM, DIM, 1, 512, 8,
                                      nullptr, nullptr);
}

// round 17
// speedup vs baseline: 1.0463x; 1.0142x over previous
#include <cuda_runtime.h>
#include <cuda_fp16.h>
#include <math.h>
#include <stdint.h>

// Problem constants
#define BATCH 2
#define TT    4096
#define DIM   1024
#define MROWS (BATCH * TT)     // 8192
#define HEADS 16
#define HS    64

// ---------------- scratch (static device globals; no allocation) ------------
__device__ __half g_xh  [(size_t)MROWS * DIM];          // LN1 out (GEMM A + residual)
__device__ __half g_qkv [(size_t)MROWS * 3 * DIM];      // [q|k|v] fp16
__device__ __half g_at  [(size_t)MROWS * 2 * DIM];      // attn out fp16
__device__ __half g_yh  [(size_t)MROWS * DIM];          // fb out fp16
__device__ __half g_zh  [(size_t)MROWS * DIM];          // LN2 out fp16
__device__ __half g_wqkvT[(size_t)(3 * DIM) * DIM];     // 3072 x 1024 (N-major)
__device__ __half g_woT [(size_t)DIM * DIM];            // 1024 x 1024
__device__ __half g_wfbT[(size_t)DIM * 2 * DIM];        // 1024 x 2048
__device__ float g_bqkv[3 * DIM];

// ---------------- PTX helpers ----------------------------------------------
__device__ __forceinline__ uint32_t s2u(const void* p) {
    uint32_t a;
    asm("{ .reg .u64 t; cvta.to.shared.u64 t, %1; cvt.u32.u64 %0, t; }"
        : "=r"(a) : "l"(p));
    return a;
}
__device__ __forceinline__ void cpa16(uint32_t s, const void* g) {
    asm volatile("cp.async.cg.shared.global [%0], [%1], 16;" :: "r"(s), "l"(g));
}
#define CP_COMMIT() asm volatile("cp.async.commit_group;" ::: "memory")
#define CP_WAIT1()  asm volatile("cp.async.wait_group 1;" ::: "memory")

#define LDSM4(r0, r1, r2, r3, addr) \
    asm volatile("ldmatrix.sync.aligned.m8n8.x4.shared.b16 {%0,%1,%2,%3}, [%4];" \
        : "=r"(r0), "=r"(r1), "=r"(r2), "=r"(r3) : "r"(addr))

#define MMA16816(d, a, b) \
    asm volatile("mma.sync.aligned.m16n8k16.row.col.f32.f16.f16.f32 " \
        "{%0,%1,%2,%3},{%4,%5,%6,%7},{%8,%9},{%0,%1,%2,%3};" \
        : "+f"((d)[0]), "+f"((d)[1]), "+f"((d)[2]), "+f"((d)[3]) \
        : "r"((a)[0]), "r"((a)[1]), "r"((a)[2]), "r"((a)[3]), \
          "r"((b)[0]), "r"((b)[1]))

// ---------------- prep: LN1 + wqkv transpose + bias concat ------------------
#define WQKV_TILES 3072             // Wq, Wk, Wv: 3 x 1024 32x32 tiles
#define BBLOCKS 12                  // 3072 / 256

__global__ void prep_kernel(const float* __restrict__ x,
                            const float* __restrict__ g1,
                            const float* __restrict__ b1,
                            __half* __restrict__ xh,
                            const float* __restrict__ Wq,
                            const float* __restrict__ Wk,
                            const float* __restrict__ Wv,
                            const float* __restrict__ bq,
                            const float* __restrict__ bk,
                            const float* __restrict__ bv,
                            float* __restrict__ bqkv)
{
    __shared__ float rs[8], rss[8];
    __shared__ float ts[32][33];
    int blk = blockIdx.x;
    int tid = threadIdx.x;

    if (blk < MROWS) {
        int row = blk;
        float4 v = ((const float4*)(x + (size_t)row * DIM))[tid];
        float s  = v.x + v.y + v.z + v.w;
        float ss = v.x*v.x + v.y*v.y + v.z*v.z + v.w*v.w;
        #pragma unroll
        for (int o = 16; o; o >>= 1) {
            s  += __shfl_xor_sync(0xffffffffu, s,  o);
            ss += __shfl_xor_sync(0xffffffffu, ss, o);
        }
        int wid = tid >> 5, lid = tid & 31;
        if (lid == 0) { rs[wid] = s; rss[wid] = ss; }
        __syncthreads();
        float tots = 0.f, totss = 0.f;
        #pragma unroll
        for (int i = 0; i < 8; i++) { tots += rs[i]; totss += rss[i]; }
        float mean = tots * (1.0f / DIM);
        float var  = totss * (1.0f / DIM) - mean * mean;
        float inv  = rsqrtf(var + 1e-6f);
        float4 gg = ((const float4*)g1)[tid], bb = ((const float4*)b1)[tid];
        float ox = (v.x - mean) * inv * gg.x + bb.x;
        float oy = (v.y - mean) * inv * gg.y + bb.y;
        float oz = (v.z - mean) * inv * gg.z + bb.z;
        float ow = (v.w - mean) * inv * gg.w + bb.w;
        __half* base = xh + (size_t)row * DIM + tid * 4;
        *(__half2*)(base)     = __halves2half2(__float2half(ox), __float2half(oy));
        *(__half2*)(base + 2) = __halves2half2(__float2half(oz), __float2half(ow));
        return;
    }
    blk -= MROWS;
    if (blk < WQKV_TILES) {
        int which = blk >> 10;
        int tile  = blk & 1023;
        const float* W = (which == 0) ? Wq : (which == 1) ? Wk : Wv;
        int nofs = which * DIM;
        int k0 = (tile >> 5) * 32;
        int n0 = (tile & 31) * 32;
        int r = tid >> 5, c = tid & 31;
        #pragma unroll
        for (int i = 0; i < 4; i++)
            ts[r + 8 * i][c] = W[(size_t)(k0 + r + 8 * i) * DIM + n0 + c];
        __syncthreads();
        #pragma unroll
        for (int i = 0; i < 4; i++) {
            int n = n0 + r + 8 * i;
            g_wqkvT[(size_t)(nofs + n) * DIM + k0 + c] = __float2half(ts[c][r + 8 * i]);
        }
        return;
    }
    blk -= WQKV_TILES;
    int i = blk * 256 + tid;
    if (i < DIM) bqkv[i] = bq[i];
    else if (i < 2 * DIM) bqkv[i] = bk[i - DIM];
    else if (i < 3 * DIM) bqkv[i] = bv[i - 2 * DIM];
}

// ---------------- LN2: fp16 y + fp16 residual -> fp16 out -------------------
__global__ void ln2_kernel(const __half* __restrict__ y,
                           const __half* __restrict__ res,
                           const float* __restrict__ g,
                           const float* __restrict__ b,
                           __half* __restrict__ h_out)
{
    __shared__ float rs[8], rss[8];
    int row = blockIdx.x;
    int tid = threadIdx.x;
    uint2 uy = ((const uint2*)(y   + (size_t)row * DIM))[tid];
    uint2 ur = ((const uint2*)(res + (size_t)row * DIM))[tid];
    float2 y0 = __half22float2(*(__half2*)&uy.x);
    float2 y1 = __half22float2(*(__half2*)&uy.y);
    float2 r0 = __half22float2(*(__half2*)&ur.x);
    float2 r1 = __half22float2(*(__half2*)&ur.y);
    float4 v = make_float4(y0.x + r0.x, y0.y + r0.y, y1.x + r1.x, y1.y + r1.y);
    float s  = v.x + v.y + v.z + v.w;
    float ss = v.x*v.x + v.y*v.y + v.z*v.z + v.w*v.w;
    #pragma unroll
    for (int o = 16; o; o >>= 1) {
        s  += __shfl_xor_sync(0xffffffffu, s,  o);
        ss += __shfl_xor_sync(0xffffffffu, ss, o);
    }
    int wid = tid >> 5, lid = tid & 31;
    if (lid == 0) { rs[wid] = s; rss[wid] = ss; }
    __syncthreads();
    float tots = 0.f, totss = 0.f;
    #pragma unroll
    for (int i = 0; i < 8; i++) { tots += rs[i]; totss += rss[i]; }
    float mean = tots * (1.0f / DIM);
    float var  = totss * (1.0f / DIM) - mean * mean;
    float inv  = rsqrtf(var + 1e-6f);
    float4 gg = ((const float4*)g)[tid], bb = ((const float4*)b)[tid];
    float ox = (v.x - mean) * inv * gg.x + bb.x;
    float oy = (v.y - mean) * inv * gg.y + bb.y;
    float oz = (v.z - mean) * inv * gg.z + bb.z;
    float ow = (v.w - mean) * inv * gg.w + bb.w;
    __half* base = h_out + (size_t)row * DIM + tid * 4;
    *(__half2*)(base)     = __halves2half2(__float2half(ox), __float2half(oy));
    *(__half2*)(base + 2) = __halves2half2(__float2half(oz), __float2half(ow));
}

// ---------------- HMMA fp16 GEMM (+ optional tail aux transposes) -----------
#define STG_OP 16384
#define GSMEM  (3 * 2 * STG_OP)      // 98304
#define AUX_WO   1024
#define AUX_WFB  2048
#define AUX_TOT  (AUX_WO + AUX_WFB)  // 3072

__device__ __forceinline__ float gelu_exact(float x) {
    return 0.5f * x * (1.0f + erff(x * 0.7071067811865475f));
}

__global__ __launch_bounds__(128, 2)
void gemm_hmma(const __half* __restrict__ A, const __half* __restrict__ B,
               const float* __restrict__ bias, void* __restrict__ Cv,
               int KK, int ldc, int epi, int ntiles, int nx,
               const float* __restrict__ WoSrc, const float* __restrict__ WfbSrc)
{
    extern __shared__ char smem[];
    const int bid = blockIdx.x;
    const int tid = threadIdx.x;

    if (bid >= ntiles) {
        // ---- aux: coalesced 32x32 transpose (128 threads, 4 rows/pass) ----
        float (*ts)[33] = (float(*)[33])smem;
        int blk = bid - ntiles;
        const float* W; __half* O; int K, tile;
        if (blk < AUX_WO) { W = WoSrc; O = g_woT; K = DIM; tile = blk; }
        else { W = WfbSrc; O = g_wfbT; K = 2 * DIM; tile = blk - AUX_WO; }
        int k0 = (tile >> 5) * 32;
        int n0 = (tile & 31) * 32;
        int r = tid >> 5, c = tid & 31;
        #pragma unroll
        for (int i = 0; i < 8; i++)
            ts[r + 4 * i][c] = W[(size_t)(k0 + r + 4 * i) * DIM + n0 + c];
        __syncthreads();
        #pragma unroll
        for (int i = 0; i < 8; i++) {
            int n = n0 + r + 4 * i;
            O[(size_t)n * K + k0 + c] = __float2half(ts[c][r + 4 * i]);
        }
        return;
    }

    const uint32_t sb = s2u(smem);
    const int wid  = tid >> 5, lane = tid & 31;
    const int bx   = bid % nx, by = bid / nx;
    const int wm   = wid & 1;
    const int wn   = wid >> 1;
    const int NT   = KK >> 6;

    uint32_t sA[3], sB[3];
    #pragma unroll
    for (int s = 0; s < 3; s++) {
        sA[s] = sb + s * 2 * STG_OP;
        sB[s] = sA[s] + STG_OP;
    }

    const int lrow = tid >> 3;
    const uint32_t ssw = ((tid & 7) * 16) ^ ((lrow & 7) << 4);
    const __half* Ag = A + (size_t)(by * 128 + lrow) * KK + (tid & 7) * 8;
    const __half* Bg = B + (size_t)(bx * 128 + lrow) * KK + (tid & 7) * 8;

    auto load_stage = [&](int s, int kt) {
        size_t kof = (size_t)kt * 64;
        #pragma unroll
        for (int i = 0; i < 8; i++)
            cpa16(sA[s] + (lrow + i * 16) * 128 + ssw, Ag + kof + (size_t)i * 16 * KK);
        #pragma unroll
        for (int i = 0; i < 8; i++)
            cpa16(sB[s] + (lrow + i * 16) * 128 + ssw, Bg + kof + (size_t)i * 16 * KK);
    };

    float acc[4][8][4];
    #pragma unroll
    for (int i = 0; i < 4; i++)
        #pragma unroll
        for (int j = 0; j < 8; j++)
            #pragma unroll
            for (int r = 0; r < 4; r++) acc[i][j][r] = 0.f;

    load_stage(0, 0); CP_COMMIT();
    load_stage(1, 1); CP_COMMIT();

    const uint32_t maskx = (lane & 7) << 4;
    const uint32_t aRow = (wm * 64 + (lane & 15)) * 128;
    const uint32_t bRow = (wn * 64 + (lane & 7) + ((lane >> 4) & 1) * 8) * 128;
    uint32_t axo[4], bxo[4];
    {
        const uint32_t aHf = (lane >> 4) * 16;
        const uint32_t bHf = ((lane >> 3) & 1) * 16;
        #pragma unroll
        for (int kh = 0; kh < 4; kh++) {
            axo[kh] = (kh * 32 + aHf) ^ maskx;
            bxo[kh] = (kh * 32 + bHf) ^ maskx;
        }
    }

    uint32_t af[2][4][4], bf[2][8][2];

    #define LD_FRAGS(buf, sAd, sBd, kh) do {                                   \
        _Pragma("unroll")                                                      \
        for (int mt = 0; mt < 4; mt++)                                         \
            LDSM4(af[buf][mt][0], af[buf][mt][1], af[buf][mt][2],              \
                  af[buf][mt][3], (sAd) + aRow + mt * 16 * 128 + axo[kh]);     \
        _Pragma("unroll")                                                      \
        for (int np = 0; np < 4; np++)                                         \
            LDSM4(bf[buf][np*2][0], bf[buf][np*2][1], bf[buf][np*2+1][0],      \
                  bf[buf][np*2+1][1], (sBd) + bRow + np * 16 * 128 + bxo[kh]); \
    } while (0)

    #define MMA_BLOCK(buf) do {                                                \
        _Pragma("unroll")                                                      \
        for (int mt = 0; mt < 4; mt++)                                         \
            _Pragma("unroll")                                                  \
            for (int nt = 0; nt < 8; nt++)                                     \
                MMA16816(acc[mt][nt], af[buf][mt], bf[buf][nt]);               \
    } while (0)

    CP_WAIT1();
    __syncthreads();
    LD_FRAGS(0, sA[0], sB[0], 0);

    for (int kt = 0; kt < NT; kt++) {
        const int s  = kt % 3;
        const int sn = (kt + 1) % 3;
        const uint32_t sAd = sA[s], sBd = sB[s];

        LD_FRAGS(1, sAd, sBd, 1);
        MMA_BLOCK(0);
        LD_FRAGS(0, sAd, sBd, 2);
        MMA_BLOCK(1);
        LD_FRAGS(1, sAd, sBd, 3);
        MMA_BLOCK(0);

        if (kt + 1 < NT) {
            CP_WAIT1();
            __syncthreads();
            if (kt + 2 < NT) load_stage((kt + 2) % 3, kt + 2);
            CP_COMMIT();
            LD_FRAGS(0, sA[sn], sB[sn], 0);   // next kt's kh0, under kh3 MMAs
        }
        MMA_BLOCK(1);
    }

    float bv0[8], bv1[8];
    #pragma unroll
    for (int nt = 0; nt < 8; nt++) {
        int col = bx * 128 + wn * 64 + nt * 8 + (lane & 3) * 2;
        bv0[nt] = __ldg(bias + col);
        bv1[nt] = __ldg(bias + col + 1);
    }
    #pragma unroll
    for (int mt = 0; mt < 4; mt++) {
        int r0 = by * 128 + wm * 64 + mt * 16 + (lane >> 2);
        #pragma unroll
        for (int nt = 0; nt < 8; nt++) {
            int col = bx * 128 + wn * 64 + nt * 8 + (lane & 3) * 2;
            float v0 = acc[mt][nt][0] + bv0[nt], v1 = acc[mt][nt][1] + bv1[nt];
            float v2 = acc[mt][nt][2] + bv0[nt], v3 = acc[mt][nt][3] + bv1[nt];
            if (epi == 1) { v0 = gelu_exact(v0); v1 = gelu_exact(v1);
                            v2 = gelu_exact(v2); v3 = gelu_exact(v3); }
            if (epi == 2) {
                __half* Ch = (__half*)Cv;
                *(__half2*)(Ch + (size_t)r0 * ldc + col) =
                    __halves2half2(__float2half(v0), __float2half(v1));
                *(__half2*)(Ch + (size_t)(r0 + 8) * ldc + col) =
                    __halves2half2(__float2half(v2), __float2half(v3));
            } else {
                float* C = (float*)Cv;
                *(float2*)(C + (size_t)r0 * ldc + col)       = make_float2(v0, v1);
                *(float2*)(C + (size_t)(r0 + 8) * ldc + col) = make_float2(v2, v3);
            }
        }
    }
    #undef LD_FRAGS
    #undef MMA_BLOCK
}

// ---------------- windowed local attention (fp16 in, fp16 out) --------------
// warp = (row, 4 heads): 8 lanes per head, each lane owns 8 dims (uint4 = 16B).
__global__ void attn_kernel(const __half* __restrict__ qkv,
                            __half* __restrict__ out)
{
    int gw   = (blockIdx.x * blockDim.x + threadIdx.x) >> 5;
    int lane = threadIdx.x & 31;
    if (gw >= MROWS * (HEADS / 4)) return;
    int quad = gw & 3;
    int row  = gw >> 2;
    int t    = row & (TT - 1);
    int off = quad * 256 + (lane >> 3) * 64 + (lane & 7) * 8;

    auto ld8 = [&](int part, int rr) -> uint4 {
        return *(const uint4*)(qkv + (size_t)rr * (3 * DIM) + part * DIM + off);
    };
    auto dot8 = [](uint4 a, uint4 b) -> float {
        float d = 0.f;
        const __half2* ah = (const __half2*)&a;
        const __half2* bh = (const __half2*)&b;
        #pragma unroll
        for (int j = 0; j < 4; j++) {
            float2 fa = __half22float2(ah[j]);
            float2 fb = __half22float2(bh[j]);
            d += fa.x * fb.x + fa.y * fb.y;
        }
        return d;
    };
    auto wsum = [](uint4 v0, uint4 v1, uint4 v2,
                   float e0, float e1, float e2) -> uint4 {
        uint4 o;
        const __half2* p0 = (const __half2*)&v0;
        const __half2* p1 = (const __half2*)&v1;
        const __half2* p2 = (const __half2*)&v2;
        __half2* po = (__half2*)&o;
        #pragma unroll
        for (int j = 0; j < 4; j++) {
            float2 f0 = __half22float2(p0[j]);
            float2 f1 = __half22float2(p1[j]);
            float2 f2 = __half22float2(p2[j]);
            float a = e0 * f0.x + e1 * f1.x + e2 * f2.x;
            float b = e0 * f0.y + e1 * f1.y + e2 * f2.y;
            po[j] = __halves2half2(__float2half(a), __float2half(b));
        }
        return o;
    };
    const uint4 zero = make_uint4(0, 0, 0, 0);

    uint4 k0 = ld8(1, row);
    uint4 v0 = ld8(2, row);

    {   // forward: query = q[t-1], keys/values rows t, t-1, t-2
        uint4 qf = (t >= 1) ? ld8(0, row - 1) : zero;
        uint4 k1 = (t >= 1) ? ld8(1, row - 1) : zero;
        uint4 k2 = (t >= 2) ? ld8(1, row - 2) : zero;
        float d0 = dot8(qf, k0), d1 = dot8(qf, k1), d2 = dot8(qf, k2);
        #pragma unroll
        for (int o = 4; o; o >>= 1) {
            d0 += __shfl_xor_sync(0xffffffffu, d0, o);
            d1 += __shfl_xor_sync(0xffffffffu, d1, o);
            d2 += __shfl_xor_sync(0xffffffffu, d2, o);
        }
        d0 *= 0.125f; d1 *= 0.125f; d2 *= 0.125f;
        float m = fmaxf(d0, fmaxf(d1, d2));
        float e0 = expf(d0-m), e1 = expf(d1-m), e2 = expf(d2-m);
        float inv = 1.0f / (e0 + e1 + e2);
        e0 *= inv; e1 *= inv; e2 *= inv;
        uint4 v1 = (t >= 1) ? ld8(2, row - 1) : zero;
        uint4 v2 = (t >= 2) ? ld8(2, row - 2) : zero;
        *(uint4*)(out + (size_t)row * (2 * DIM) + off) = wsum(v0, v1, v2, e0, e1, e2);
    }
    {   // reverse: query = q[t+1], keys/values rows t, t+1, t+2
        uint4 qr = (t + 1 < TT) ? ld8(0, row + 1) : zero;
        uint4 k1 = (t + 1 < TT) ? ld8(1, row + 1) : zero;
        uint4 k2 = (t + 2 < TT) ? ld8(1, row + 2) : zero;
        float d0 = dot8(qr, k0), d1 = dot8(qr, k1), d2 = dot8(qr, k2);
        #pragma unroll
        for (int o = 4; o; o >>= 1) {
            d0 += __shfl_xor_sync(0xffffffffu, d0, o);
            d1 += __shfl_xor_sync(0xffffffffu, d1, o);
            d2 += __shfl_xor_sync(0xffffffffu, d2, o);
        }
        d0 *= 0.125f; d1 *= 0.125f; d2 *= 0.125f;
        float m = fmaxf(d0, fmaxf(d1, d2));
        float e0 = expf(d0-m), e1 = expf(d1-m), e2 = expf(d2-m);
        float inv = 1.0f / (e0 + e1 + e2);
        e0 *= inv; e1 *= inv; e2 *= inv;
        uint4 v1 = (t + 1 < TT) ? ld8(2, row + 1) : zero;
        uint4 v2 = (t + 2 < TT) ? ld8(2, row + 2) : zero;
        *(uint4*)(out + (size_t)row * (2 * DIM) + DIM + off) = wsum(v0, v1, v2, e0, e1, e2);
    }
}

// ---------------- launch ----------------------------------------------------
extern "C" void kernel_launch(void* const* d_in, const int* in_sizes, int n_in,
                              void* d_out, int out_size)
{
    const float* x   = (const float*)d_in[0];
    const float* Wq  = (const float*)d_in[1];
    const float* bq  = (const float*)d_in[2];
    const float* Wk  = (const float*)d_in[3];
    const float* bk  = (const float*)d_in[4];
    const float* Wv  = (const float*)d_in[5];
    const float* bv  = (const float*)d_in[6];
    const float* Wfb = (const float*)d_in[7];
    const float* bfb = (const float*)d_in[8];
    const float* Wo  = (const float*)d_in[9];
    const float* bo  = (const float*)d_in[10];
    const float* g1  = (const float*)d_in[11];
    const float* b1  = (const float*)d_in[12];
    const float* g2  = (const float*)d_in[13];
    const float* b2  = (const float*)d_in[14];
    float* out = (float*)d_out;

    void *p;
    float *bqkv;
    __half *xh, *qkv, *at, *yh, *zh, *wqkvT, *woT, *wfbT;
    cudaGetSymbolAddress(&p, g_bqkv);  bqkv  = (float*)p;
    cudaGetSymbolAddress(&p, g_xh);    xh    = (__half*)p;
    cudaGetSymbolAddress(&p, g_qkv);   qkv   = (__half*)p;
    cudaGetSymbolAddress(&p, g_at);    at    = (__half*)p;
    cudaGetSymbolAddress(&p, g_yh);    yh    = (__half*)p;
    cudaGetSymbolAddress(&p, g_zh);    zh    = (__half*)p;
    cudaGetSymbolAddress(&p, g_wqkvT); wqkvT = (__half*)p;
    cudaGetSymbolAddress(&p, g_woT);   woT   = (__half*)p;
    cudaGetSymbolAddress(&p, g_wfbT);  wfbT  = (__half*)p;

    cudaFuncSetAttribute(gemm_hmma, cudaFuncAttributeMaxDynamicSharedMemorySize, GSMEM);

    // 0) prep: LN1 + wqkv transpose + bias concat
    prep_kernel<<<MROWS + WQKV_TILES + BBLOCKS, 256>>>(
        x, g1, b1, xh, Wq, Wk, Wv, bq, bk, bv, bqkv);

    // 1) fused qkv GEMM (1536 tiles) + tail aux: Wo/Wfb transposes (3072 blks)
    gemm_hmma<<<1536 + AUX_TOT, 128, GSMEM>>>(
        xh, wqkvT, bqkv, qkv, DIM, 3*DIM, 2, 1536, 24, Wo, Wfb);

    // 2) local attention (fp16 -> fp16), warp = 4 heads
    attn_kernel<<<(MROWS*(HEADS/4)*32)/256, 256>>>(qkv, at);

    // 3) y = at @ Wfb + bfb, K=2048, fp16 out
    gemm_hmma<<<512, 128, GSMEM>>>(at, wfbT, bfb, yh, 2*DIM, DIM, 2, 512, 8,
                                   nullptr, nullptr);
    // 4) LN2(y + xh) -> fp16
    ln2_kernel<<<MROWS, 256>>>(yh, xh, g2, b2, zh);
    // 5) out = gelu(z @ Wo + bo), K=1024, fp32+gelu
    gemm_hmma<<<512, 128, GSMEM>>>(zh, woT, bo, out, DIM, DIM, 1, 512, 8,
                                   nullptr, nullptr);
}